// round 9
// baseline (speedup 1.0000x reference)
#include <cuda_runtime.h>
#include <cuda_bf16.h>

#define PAD_VAL  -1000.0f
#define ROW      4096
#define NROWS    1024
#define SEGF     1024          // floats per block segment
#define NSEG     (ROW / SEGF)  // 4
#define NCHK     256           // owned 4-float chunks per block
#define HALO     16            // halo chunks (next 64 floats)
#define THREADS  256

// out[i] = relu( max_{j=1..64}(h[i+j]-j) - h[i] ), right-pad -1000.
// Thread t owns chunk c = t: 4 contiguous floats (coalesced float4 IO).
// Per-chunk local frame g[q] = h[4c+q] - q (q<4, offsets tiny -> fp32-exact):
//   out[j] = relu( max( suf_c(j+1),
//                       max_{k=1..15}( M[c+k] - 4k ),
//                       pre_j[c+16] - 64 ) - g[j] )
// Only 5 floats/chunk of summary go through smem (stride-1, conflict-free);
// bulk data stays in registers. One barrier. Halo chunks of the last segment
// are the -1000 sentinel (exact reference pad semantics).
__global__ __launch_bounds__(THREADS, 8) void h2i_kernel(
    const float* __restrict__ hf, float* __restrict__ out)
{
    const int t   = threadIdx.x;              // chunk id within segment
    const int row = blockIdx.x >> 2;
    const int seg = blockIdx.x & (NSEG - 1);
    const size_t base = (size_t)row * ROW + seg * SEGF;

    __shared__ float sM [NCHK + HALO];
    __shared__ float sP0[NCHK + HALO];
    __shared__ float sP1[NCHK + HALO];
    __shared__ float sP2[NCHK + HALO];
    __shared__ float sP3[NCHK + HALO];

    // ---- own chunk: one coalesced LDG.128, reindex, prefix maxes ----
    float4 a = ((const float4*)(hf + base))[t];
    const float g0 = a.x, g1 = a.y - 1.0f, g2 = a.z - 2.0f, g3 = a.w - 3.0f;
    const float p1 = fmaxf(g0, g1), p2 = fmaxf(p1, g2), p3 = fmaxf(p2, g3);
    sP0[t] = g0; sP1[t] = p1; sP2[t] = p2; sP3[t] = p3; sM[t] = p3;

    // ---- halo chunks: threads 0..15 (coalesced 64-float read or sentinel) ----
    if (t < HALO) {
        float h0, h1, h2, h3;
        if (seg < NSEG - 1) {
            float4 b = ((const float4*)(hf + base + SEGF))[t];
            h0 = b.x; h1 = b.y - 1.0f; h2 = b.z - 2.0f; h3 = b.w - 3.0f;
        } else {
            h0 = PAD_VAL; h1 = PAD_VAL - 1.0f;
            h2 = PAD_VAL - 2.0f; h3 = PAD_VAL - 3.0f;
        }
        const float q1 = fmaxf(h0, h1), q2 = fmaxf(q1, h2), q3 = fmaxf(q2, h3);
        sP0[NCHK + t] = h0; sP1[NCHK + t] = q1;
        sP2[NCHK + t] = q2; sP3[NCHK + t] = q3;
        sM[NCHK + t]  = q3;
    }
    __syncthreads();

    // ---- mid = max of whole chunks c+1..c+15 (15 stride-1 LDS) ----
    float mid = sM[t + 1] - 4.0f;
    #pragma unroll
    for (int k = 2; k <= 15; k++)
        mid = fmaxf(mid, sM[t + k] - (float)(4 * k));

    // ---- B_j = prefix of chunk c+16 through element j ----
    const float B0 = sP0[t + 16] - 64.0f;
    const float B1 = sP1[t + 16] - 64.0f;
    const float B2 = sP2[t + 16] - 64.0f;
    const float B3 = sP3[t + 16] - 64.0f;

    // ---- own-chunk suffixes + combine (j=3 has no own suffix) ----
    const float suf2 = g3;
    const float suf1 = fmaxf(g2, suf2);
    const float suf0 = fmaxf(g1, suf1);

    float w, r0, r1, r2, r3;
    w = fmaxf(fmaxf(suf0, mid), B0); r0 = fmaxf(w - g0, 0.0f);
    w = fmaxf(fmaxf(suf1, mid), B1); r1 = fmaxf(w - g1, 0.0f);
    w = fmaxf(fmaxf(suf2, mid), B2); r2 = fmaxf(w - g2, 0.0f);
    w = fmaxf(mid, B3);              r3 = fmaxf(w - g3, 0.0f);

    // ---- one coalesced STG.128 ----
    ((float4*)(out + base))[t] = make_float4(r0, r1, r2, r3);
}

extern "C" void kernel_launch(void* const* d_in, const int* in_sizes, int n_in,
                              void* d_out, int out_size)
{
    const float* hf  = (const float*)d_in[0];
    float*       out = (float*)d_out;
    (void)in_sizes; (void)n_in; (void)out_size;
    // 1024 rows x 4 segments = 4096 blocks x 256 threads
    h2i_kernel<<<NROWS * NSEG, THREADS>>>(hf, out);
}

// round 10
// speedup vs baseline: 1.0396x; 1.0396x over previous
#include <cuda_runtime.h>
#include <cuda_bf16.h>

#define PAD_VAL  -1000.0f
#define ROW      4096
#define NROWS    1024
#define SEGF     1024          // floats per segment
#define NSEG     4             // segments per row
#define NCHK     256           // owned 4-float chunks per segment
#define HALO     16            // halo chunks (next 64 floats)
#define RPB      4             // rows per block (per-thread ILP)
#define PLANE    (NCHK + HALO) // 272
#define THREADS  256

// out[i] = relu( max_{j=1..64}(h[i+j]-j) - h[i] ), right-pad -1000.
// Block = (row-group of 4, segment). Thread t owns chunk t (4 contiguous
// floats, coalesced float4) in ALL 4 rows -> 4 independent front-batched
// LDG.128 per thread; the barrier amortizes over 4x work. Decomposition
// identical to R9 (rel_err 9e-8): g[q] = h[4c+q]-q,
//   out[j] = relu( max( suf_c(j+1), max_{k=1..15}(M[c+k]-4k),
//                       pre_j[c+16]-64 ) - g[j] )
// 4 smem summary planes per row (prefix0..3; chunk max = plane3).
__global__ __launch_bounds__(THREADS, 6) void h2i_kernel(
    const float* __restrict__ hf, float* __restrict__ out)
{
    const int t   = threadIdx.x;
    const int rg  = blockIdx.x >> 2;            // row group
    const int seg = blockIdx.x & (NSEG - 1);
    const size_t base0 = ((size_t)rg * RPB) * ROW + (size_t)seg * SEGF;

    __shared__ float sP0[RPB][PLANE];
    __shared__ float sP1[RPB][PLANE];
    __shared__ float sP2[RPB][PLANE];
    __shared__ float sP3[RPB][PLANE];

    // ---- 4 independent main loads, front-batched (MLP=4 per thread) ----
    float4 a[RPB];
    #pragma unroll
    for (int j = 0; j < RPB; j++)
        a[j] = ((const float4*)(hf + base0 + (size_t)j * ROW))[t];

    // ---- halo: threads 0..63, one chunk each (row j = t/16, chunk t%16) ----
    float4 hr;
    const int hj = t >> 4, ht = t & 15;
    if (t < 64) {
        if (seg < NSEG - 1)
            hr = ((const float4*)(hf + base0 + (size_t)hj * ROW + SEGF))[ht];
        else
            hr = make_float4(PAD_VAL, PAD_VAL, PAD_VAL, PAD_VAL);
    }

    // ---- reindex + prefix maxes -> summary planes (in-place a -> g) ----
    float g[RPB][4];
    #pragma unroll
    for (int j = 0; j < RPB; j++) {
        g[j][0] = a[j].x;        g[j][1] = a[j].y - 1.0f;
        g[j][2] = a[j].z - 2.0f; g[j][3] = a[j].w - 3.0f;
        const float p1 = fmaxf(g[j][0], g[j][1]);
        const float p2 = fmaxf(p1, g[j][2]);
        const float p3 = fmaxf(p2, g[j][3]);
        sP0[j][t] = g[j][0]; sP1[j][t] = p1; sP2[j][t] = p2; sP3[j][t] = p3;
    }
    if (t < 64) {
        const float h0 = hr.x, h1 = hr.y - 1.0f, h2 = hr.z - 2.0f, h3 = hr.w - 3.0f;
        const float q1 = fmaxf(h0, h1), q2 = fmaxf(q1, h2), q3 = fmaxf(q2, h3);
        sP0[hj][NCHK + ht] = h0; sP1[hj][NCHK + ht] = q1;
        sP2[hj][NCHK + ht] = q2; sP3[hj][NCHK + ht] = q3;
    }
    __syncthreads();

    // ---- combine + store, 4 rows back-to-back (long issue stream) ----
    #pragma unroll
    for (int j = 0; j < RPB; j++) {
        float mid = sP3[j][t + 1] - 4.0f;
        #pragma unroll
        for (int k = 2; k <= 15; k++)
            mid = fmaxf(mid, sP3[j][t + k] - (float)(4 * k));

        const float B0 = sP0[j][t + 16] - 64.0f;
        const float B1 = sP1[j][t + 16] - 64.0f;
        const float B2 = sP2[j][t + 16] - 64.0f;
        const float B3 = sP3[j][t + 16] - 64.0f;

        const float suf2 = g[j][3];
        const float suf1 = fmaxf(g[j][2], suf2);
        const float suf0 = fmaxf(g[j][1], suf1);

        float w, r0, r1, r2, r3;
        w = fmaxf(fmaxf(suf0, mid), B0); r0 = fmaxf(w - g[j][0], 0.0f);
        w = fmaxf(fmaxf(suf1, mid), B1); r1 = fmaxf(w - g[j][1], 0.0f);
        w = fmaxf(fmaxf(suf2, mid), B2); r2 = fmaxf(w - g[j][2], 0.0f);
        w = fmaxf(mid, B3);              r3 = fmaxf(w - g[j][3], 0.0f);

        ((float4*)(out + base0 + (size_t)j * ROW))[t] = make_float4(r0, r1, r2, r3);
    }
}

extern "C" void kernel_launch(void* const* d_in, const int* in_sizes, int n_in,
                              void* d_out, int out_size)
{
    const float* hf  = (const float*)d_in[0];
    float*       out = (float*)d_out;
    (void)in_sizes; (void)n_in; (void)out_size;
    // Hint max smem carveout so 6 blocks x ~18.4KB can co-reside per SM.
    cudaFuncSetAttribute(h2i_kernel,
                         cudaFuncAttributePreferredSharedMemoryCarveout,
                         cudaSharedmemCarveoutMaxShared);
    // 256 row-groups x 4 segments = 1024 blocks
    h2i_kernel<<<(NROWS / RPB) * NSEG, THREADS>>>(hf, out);
}